// round 6
// baseline (speedup 1.0000x reference)
#include <cuda_runtime.h>
#include <math.h>

#define BB 64
#define TT 512
#define DI 256
#define HH 512
#define GG 2048   // 4*HH
#define OO 128
#define NCTA 128  // persistent grid

// ---------------- scratch (static device globals) ----------------
__device__ float g_gx[(size_t)TT * BB * GG];     // [t][b][n], n = j*4+gate
__device__ float g_hseq0[(size_t)TT * BB * HH];  // layer0 h sequence [t][b][j]
__device__ float g_Wih0r[GG * DI];
__device__ float g_Whh0r[GG * HH];
__device__ float g_Wih1r[GG * HH];
__device__ float g_Whh1r[GG * HH];
__device__ float g_bias0[GG];
__device__ float g_bias1[GG];
__device__ float g_h[2 * BB * HH];
__device__ float g_c[2 * BB * HH];
__device__ float g_hT[2 * HH * BB];              // ping-pong h transposed [buf][j][b]
__device__ unsigned g_ctr[2];

// ---------------- f32x2 helpers ----------------
__device__ __forceinline__ void ffma2(unsigned long long& acc, unsigned long long a,
                                      unsigned long long b) {
    asm("fma.rn.f32x2 %0, %1, %2, %0;" : "+l"(acc) : "l"(a), "l"(b));
}
__device__ __forceinline__ float2 unpk(unsigned long long v) {
    float2 r;
    asm("mov.b64 {%0, %1}, %2;" : "=f"(r.x), "=f"(r.y) : "l"(v));
    return r;
}

// ---------------- prep: barrier ctrs + folded biases ----------------
__global__ void prep_misc(const float* __restrict__ bi0, const float* __restrict__ bh0,
                          const float* __restrict__ bi1, const float* __restrict__ bh1) {
    int idx = blockIdx.x * blockDim.x + threadIdx.x;
    if (idx < 2) g_ctr[idx] = 0u;
    if (idx < GG) {
        int g = idx >> 9, j = idx & 511;
        g_bias0[j * 4 + g] = bi0[idx] + bh0[idx];
    } else if (idx < 2 * GG) {
        int n = idx - GG;
        int g = n >> 9, j = n & 511;
        g_bias1[j * 4 + g] = bi1[n] + bh1[n];
    }
}

// ---------------- all weight reorders in one kernel ----------------
__global__ void reorder_all(const float* __restrict__ Wih0, const float* __restrict__ Whh0,
                            const float* __restrict__ Wih1, const float* __restrict__ Whh1) {
    int idx = blockIdx.x * blockDim.x + threadIdx.x;
    if (idx < GG * DI) {
        int k = idx % DI, n_old = idx / DI;
        int g = n_old >> 9, j = n_old & 511;
        g_Wih0r[(j * 4 + g) * DI + k] = Wih0[idx];
        return;
    }
    idx -= GG * DI;
    if (idx < GG * HH) {
        int k = idx % HH, n_old = idx / HH;
        int g = n_old >> 9, j = n_old & 511;
        g_Whh0r[(j * 4 + g) * HH + k] = Whh0[idx];
        return;
    }
    idx -= GG * HH;
    if (idx < GG * HH) {
        int k = idx % HH, n_old = idx / HH;
        int g = n_old >> 9, j = n_old & 511;
        g_Wih1r[(j * 4 + g) * HH + k] = Wih1[idx];
        return;
    }
    idx -= GG * HH;
    if (idx < GG * HH) {
        int k = idx % HH, n_old = idx / HH;
        int g = n_old >> 9, j = n_old & 511;
        g_Whh1r[(j * 4 + g) * HH + k] = Whh1[idx];
    }
}

// ---------------- input GEMM (f32x2): gx[m][n] = A[m,:].Wr[n,:] + bias[n] ----------------
template <int LAYER>
__global__ void __launch_bounds__(256) gemm_input(const float* __restrict__ X) {
    constexpr int K = (LAYER == 0) ? DI : HH;
    const float* __restrict__ Wr   = (LAYER == 0) ? g_Wih0r : g_Wih1r;
    const float* __restrict__ bias = (LAYER == 0) ? g_bias0 : g_bias1;

    __shared__ float2 As2[8][128];   // duplicated pairs (a,a)
    __shared__ float  Bs[8][128];

    const int tm = blockIdx.y * 128, tn = blockIdx.x * 128;
    const int tid = threadIdx.x;
    const int tx = tid & 15, ty = tid >> 4;
    const int lm = tid >> 1, lk = (tid & 1) * 4;

    const float* Arow;
    if (LAYER == 0) {
        int m = tm + lm;
        int b = m & 63, t = m >> 6;               // x layout [b][t][i]
        Arow = X + (size_t)(b * TT + t) * K;
    } else {
        Arow = g_hseq0 + (size_t)(tm + lm) * K;   // [t][b][k]
    }
    const float* Brow = Wr + (size_t)(tn + lm) * K;

    unsigned long long acc2[8][4];
#pragma unroll
    for (int r = 0; r < 8; r++)
#pragma unroll
        for (int c = 0; c < 4; c++) acc2[r][c] = 0ull;

    const float4 bias0 = *(const float4*)&bias[tn + tx * 8];
    const float4 bias1 = *(const float4*)&bias[tn + tx * 8 + 4];

    for (int k0 = 0; k0 < K; k0 += 8) {
        float4 av = *(const float4*)(Arow + k0 + lk);
        float4 bv = *(const float4*)(Brow + k0 + lk);
        __syncthreads();
        As2[lk + 0][lm] = make_float2(av.x, av.x);
        As2[lk + 1][lm] = make_float2(av.y, av.y);
        As2[lk + 2][lm] = make_float2(av.z, av.z);
        As2[lk + 3][lm] = make_float2(av.w, av.w);
        Bs[lk + 0][lm] = bv.x; Bs[lk + 1][lm] = bv.y;
        Bs[lk + 2][lm] = bv.z; Bs[lk + 3][lm] = bv.w;
        __syncthreads();
#pragma unroll
        for (int kk = 0; kk < 8; kk++) {
            ulonglong2 a01 = *(const ulonglong2*)&As2[kk][ty * 8 + 0];
            ulonglong2 a23 = *(const ulonglong2*)&As2[kk][ty * 8 + 2];
            ulonglong2 a45 = *(const ulonglong2*)&As2[kk][ty * 8 + 4];
            ulonglong2 a67 = *(const ulonglong2*)&As2[kk][ty * 8 + 6];
            ulonglong2 b03 = *(const ulonglong2*)&Bs[kk][tx * 8];
            ulonglong2 b47 = *(const ulonglong2*)&Bs[kk][tx * 8 + 4];
            unsigned long long ar[8] = {a01.x, a01.y, a23.x, a23.y, a45.x, a45.y, a67.x, a67.y};
            unsigned long long bp[4] = {b03.x, b03.y, b47.x, b47.y};
#pragma unroll
            for (int r = 0; r < 8; r++) {
                ffma2(acc2[r][0], ar[r], bp[0]);
                ffma2(acc2[r][1], ar[r], bp[1]);
                ffma2(acc2[r][2], ar[r], bp[2]);
                ffma2(acc2[r][3], ar[r], bp[3]);
            }
        }
    }

#pragma unroll
    for (int r = 0; r < 8; r++) {
        float2 p0 = unpk(acc2[r][0]), p1 = unpk(acc2[r][1]);
        float2 p2 = unpk(acc2[r][2]), p3 = unpk(acc2[r][3]);
        float4 o0 = make_float4(p0.x + bias0.x, p0.y + bias0.y, p1.x + bias0.z, p1.y + bias0.w);
        float4 o1 = make_float4(p2.x + bias1.x, p2.y + bias1.y, p3.x + bias1.z, p3.y + bias1.w);
        size_t m = (size_t)tm + ty * 8 + r;
        float4* crow = (float4*)(g_gx + m * GG + tn + tx * 8);
        crow[0] = o0;
        crow[1] = o1;
    }
}

// ---------------- persistent recurrence (f32x2, chunked double-buffered staging) -----------
// 128 CTAs x 256 threads. CTA owns 16 gate-cols (4 hidden units j).
// smem: Ws2 (duplicated Whh pairs) 64KB, hs 2x(64k x 64b) 32KB, Cs[2][64][20] 10KB.
template <int LAYER>
__global__ void __launch_bounds__(256, 1) lstm_persist(float* __restrict__ lstm_out) {
    extern __shared__ float smem[];
    float2* Ws2 = (float2*)smem;                  // [512][16] pairs
    float*  hs  = smem + 512 * 16 * 2;            // 2 * 4096 floats
    float*  Cs  = hs + 2 * 4096;                  // [2][64][20]

    const int tid = threadIdx.x;
    const int cta = blockIdx.x;
    const int nbase = cta * 16;
    const int jbase = cta * 4;
    const float* __restrict__ Whh = LAYER ? g_Whh1r : g_Whh0r;

    // GEMM role: split-K x2 (even/odd k), thread tile 4m x 2n
    const int kh = tid >> 7;            // 0/1
    const int t2 = tid & 127;
    const int n2 = t2 & 7;              // column pair index (cols 2n2, 2n2+1)
    const int m0 = (t2 >> 3) * 4;       // 4 batch rows
    // pointwise role
    const int pm = tid >> 2;            // batch 0..63
    const int jl = tid & 3;             // unit 0..3

    // stage duplicated Whh slice once: Ws2[k][nl] = (w,w)
    for (int i = tid; i < 512 * 16; i += 256) {
        int k = i & 511, nl = i >> 9;
        float w = Whh[(size_t)(nbase + nl) * HH + k];
        Ws2[k * 16 + nl] = make_float2(w, w);
    }

    float c_reg = 0.f;

    for (int t = 0; t < TT; ++t) {
        if (t > 0) {
            const float4* hsrc = (const float4*)(g_hT + ((t - 1) & 1) * (HH * BB));
            // prologue: stage chunk 0
            float4 p0 = __ldcg(hsrc + tid);
            float4 p1 = __ldcg(hsrc + tid + 256);
            float4 p2 = __ldcg(hsrc + tid + 512);
            float4 p3 = __ldcg(hsrc + tid + 768);
            {
                float4* d = (float4*)hs;
                d[tid] = p0; d[tid + 256] = p1; d[tid + 512] = p2; d[tid + 768] = p3;
            }
            __syncthreads();

            unsigned long long aA = 0, aB = 0, aC = 0, aD = 0;
#pragma unroll
            for (int c = 0; c < 8; c++) {
                if (c < 7) {
                    const float4* s = hsrc + (c + 1) * 1024;
                    p0 = __ldcg(s + tid);
                    p1 = __ldcg(s + tid + 256);
                    p2 = __ldcg(s + tid + 512);
                    p3 = __ldcg(s + tid + 768);
                }
                const float2* wp = Ws2 + (c * 64 + kh) * 16 + n2 * 2;
                const float*  hp = hs + (c & 1) * 4096 + kh * 64 + m0;
#pragma unroll
                for (int i = 0; i < 32; i++) {
                    ulonglong2 w2 = *(const ulonglong2*)(wp + i * 32);
                    ulonglong2 h2 = *(const ulonglong2*)(hp + i * 128);
                    ffma2(aA, h2.x, w2.x);
                    ffma2(aB, h2.y, w2.x);
                    ffma2(aC, h2.x, w2.y);
                    ffma2(aD, h2.y, w2.y);
                }
                if (c < 7) {
                    float4* d = (float4*)(hs + ((c + 1) & 1) * 4096);
                    d[tid] = p0; d[tid + 256] = p1; d[tid + 512] = p2; d[tid + 768] = p3;
                    __syncthreads();
                }
            }

            float2 vA = unpk(aA), vB = unpk(aB), vC = unpk(aC), vD = unpk(aD);
            float* cr = Cs + (kh * 64 + m0) * 20 + n2 * 2;
            cr[0]  = vA.x; cr[1]       = vC.x;
            cr[20] = vA.y; cr[21]      = vC.y;
            cr[40] = vB.x; cr[41]      = vC.x * 0.f + vD.x;  // (kept simple below)
            cr[60] = vB.y; cr[61]      = vD.y;
            // fix row for m0+2 col n+1 (written above as vD.x)
            __syncthreads();
        }

        // gate pre-activations
        float4 gg = *(const float4*)(g_gx + (((size_t)t * BB + pm) * GG + nbase + 4 * jl));
        if (t > 0) {
            float4 c0 = *(const float4*)&Cs[pm * 20 + 4 * jl];
            float4 c1 = *(const float4*)&Cs[(64 + pm) * 20 + 4 * jl];
            gg.x += c0.x + c1.x;
            gg.y += c0.y + c1.y;
            gg.z += c0.z + c1.z;
            gg.w += c0.w + c1.w;
        }

        float si = 1.f / (1.f + expf(-gg.x));
        float sf = 1.f / (1.f + expf(-gg.y));
        float tg = tanhf(gg.z);
        float so = 1.f / (1.f + expf(-gg.w));
        c_reg = fmaf(sf, c_reg, si * tg);
        float hn = so * tanhf(c_reg);

        int j = jbase + jl;
        g_hT[(t & 1) * (HH * BB) + j * 64 + pm] = hn;
        if (LAYER == 0) g_hseq0[((size_t)t * BB + pm) * HH + j] = hn;      // [t][b][j]
        else            lstm_out[((size_t)pm * TT + t) * HH + j] = hn;     // [b][t][j]
        if (t == TT - 1) {
            g_h[LAYER * (BB * HH) + pm * HH + j] = hn;
            g_c[LAYER * (BB * HH) + pm * HH + j] = c_reg;
        }

        // grid barrier
        __syncthreads();
        if (tid == 0) {
            __threadfence();
            unsigned target = (unsigned)NCTA * (unsigned)(t + 1);
            unsigned a = atomicAdd(&g_ctr[LAYER], 1u) + 1u;
            if (a < target) {
                volatile unsigned* p = &g_ctr[LAYER];
                while (*p < target) __nanosleep(64);
            }
            __threadfence();
        }
        __syncthreads();
    }
}

// ---------------- epilogue ----------------
__global__ void out_proj(const float* __restrict__ Wout, const float* __restrict__ bout,
                         float* __restrict__ out) {
    int b = blockIdx.x;
    int o = threadIdx.x;
    const float4* hrow = (const float4*)(g_h + BB * HH + b * HH);
    const float4* w = (const float4*)(Wout + o * HH);
    float s = 0.f;
#pragma unroll 4
    for (int k = 0; k < HH / 4; k++) {
        float4 hv = hrow[k];
        float4 wv = w[k];
        s = fmaf(hv.x, wv.x, s);
        s = fmaf(hv.y, wv.y, s);
        s = fmaf(hv.z, wv.z, s);
        s = fmaf(hv.w, wv.w, s);
    }
    out[b * OO + o] = s + bout[o];
}

__global__ void copy_states(float* __restrict__ hidden, float* __restrict__ cell) {
    int idx = blockIdx.x * blockDim.x + threadIdx.x;
    if (idx < 2 * BB * HH) {
        hidden[idx] = g_h[idx];
        cell[idx]   = g_c[idx];
    }
}

// ---------------- launch ----------------
extern "C" void kernel_launch(void* const* d_in, const int* in_sizes, int n_in,
                              void* d_out, int out_size) {
    const float* x     = (const float*)d_in[0];
    const float* W_ih0 = (const float*)d_in[1];
    const float* W_hh0 = (const float*)d_in[2];
    const float* b_ih0 = (const float*)d_in[3];
    const float* b_hh0 = (const float*)d_in[4];
    const float* W_ih1 = (const float*)d_in[5];
    const float* W_hh1 = (const float*)d_in[6];
    const float* b_ih1 = (const float*)d_in[7];
    const float* b_hh1 = (const float*)d_in[8];
    const float* W_out = (const float*)d_in[9];
    const float* b_out = (const float*)d_in[10];

    float* out      = (float*)d_out;
    float* lstm_out = out + BB * OO;
    float* hidden   = lstm_out + (size_t)BB * TT * HH;
    float* cell     = hidden + 2 * BB * HH;

    const int SMEM = (512 * 16 * 2 + 2 * 4096 + 2 * 64 * 20) * 4;   // 108,544 B
    cudaFuncSetAttribute(lstm_persist<0>, cudaFuncAttributeMaxDynamicSharedMemorySize, SMEM);
    cudaFuncSetAttribute(lstm_persist<1>, cudaFuncAttributeMaxDynamicSharedMemorySize, SMEM);

    prep_misc<<<(2 * GG + 255) / 256, 256>>>(b_ih0, b_hh0, b_ih1, b_hh1);
    reorder_all<<<(GG * DI + 3 * GG * HH + 255) / 256, 256>>>(W_ih0, W_hh0, W_ih1, W_hh1);

    gemm_input<0><<<dim3(GG / 128, (TT * BB) / 128), 256>>>(x);
    lstm_persist<0><<<NCTA, 256, SMEM>>>(lstm_out);

    gemm_input<1><<<dim3(GG / 128, (TT * BB) / 128), 256>>>(x);
    lstm_persist<1><<<NCTA, 256, SMEM>>>(lstm_out);

    out_proj<<<BB, OO>>>(W_out, b_out, out);
    copy_states<<<(2 * BB * HH + 255) / 256, 256>>>(hidden, cell);
}

// round 7
// speedup vs baseline: 1.0516x; 1.0516x over previous
#include <cuda_runtime.h>
#include <math.h>

#define BB 64
#define TT 512
#define DI 256
#define HH 512
#define GG 2048   // 4*HH
#define OO 128
#define NCTA 128  // persistent grid

// ---------------- scratch (static device globals) ----------------
__device__ float g_gx[(size_t)TT * BB * GG];     // [t][b][n], n = j*4+gate
__device__ float g_hseq0[(size_t)TT * BB * HH];  // layer0 h sequence [t][b][j]
__device__ float g_Wih0r[GG * DI];
__device__ float g_Whh0r[GG * HH];
__device__ float g_Wih1r[GG * HH];
__device__ float g_Whh1r[GG * HH];
__device__ float g_bias0[GG];
__device__ float g_bias1[GG];
__device__ float g_h[2 * BB * HH];
__device__ float g_c[2 * BB * HH];
__device__ float g_hT[2 * HH * BB];              // ping-pong h transposed [buf][j][b]
__device__ unsigned g_ctr[2];

// ---------------- f32x2 helpers ----------------
__device__ __forceinline__ void ffma2(unsigned long long& acc, unsigned long long a,
                                      unsigned long long b) {
    asm("fma.rn.f32x2 %0, %1, %2, %0;" : "+l"(acc) : "l"(a), "l"(b));
}
__device__ __forceinline__ float2 unpk(unsigned long long v) {
    float2 r;
    asm("mov.b64 {%0, %1}, %2;" : "=f"(r.x), "=f"(r.y) : "l"(v));
    return r;
}

// ---------------- prep: barrier ctrs + folded biases ----------------
__global__ void prep_misc(const float* __restrict__ bi0, const float* __restrict__ bh0,
                          const float* __restrict__ bi1, const float* __restrict__ bh1) {
    int idx = blockIdx.x * blockDim.x + threadIdx.x;
    if (idx < 2) g_ctr[idx] = 0u;
    if (idx < GG) {
        int g = idx >> 9, j = idx & 511;
        g_bias0[j * 4 + g] = bi0[idx] + bh0[idx];
    } else if (idx < 2 * GG) {
        int n = idx - GG;
        int g = n >> 9, j = n & 511;
        g_bias1[j * 4 + g] = bi1[n] + bh1[n];
    }
}

// ---------------- all weight reorders in one kernel ----------------
__global__ void reorder_all(const float* __restrict__ Wih0, const float* __restrict__ Whh0,
                            const float* __restrict__ Wih1, const float* __restrict__ Whh1) {
    int idx = blockIdx.x * blockDim.x + threadIdx.x;
    if (idx < GG * DI) {
        int k = idx % DI, n_old = idx / DI;
        int g = n_old >> 9, j = n_old & 511;
        g_Wih0r[(j * 4 + g) * DI + k] = Wih0[idx];
        return;
    }
    idx -= GG * DI;
    if (idx < GG * HH) {
        int k = idx % HH, n_old = idx / HH;
        int g = n_old >> 9, j = n_old & 511;
        g_Whh0r[(j * 4 + g) * HH + k] = Whh0[idx];
        return;
    }
    idx -= GG * HH;
    if (idx < GG * HH) {
        int k = idx % HH, n_old = idx / HH;
        int g = n_old >> 9, j = n_old & 511;
        g_Wih1r[(j * 4 + g) * HH + k] = Wih1[idx];
        return;
    }
    idx -= GG * HH;
    if (idx < GG * HH) {
        int k = idx % HH, n_old = idx / HH;
        int g = n_old >> 9, j = n_old & 511;
        g_Whh1r[(j * 4 + g) * HH + k] = Whh1[idx];
    }
}

// ---------------- input GEMM (f32x2): gx[m][n] = A[m,:].Wr[n,:] + bias[n] ----------------
template <int LAYER>
__global__ void __launch_bounds__(256) gemm_input(const float* __restrict__ X) {
    constexpr int K = (LAYER == 0) ? DI : HH;
    const float* __restrict__ Wr   = (LAYER == 0) ? g_Wih0r : g_Wih1r;
    const float* __restrict__ bias = (LAYER == 0) ? g_bias0 : g_bias1;

    __shared__ float2 As2[8][128];   // duplicated pairs (a,a)
    __shared__ float  Bs[8][128];

    const int tm = blockIdx.y * 128, tn = blockIdx.x * 128;
    const int tid = threadIdx.x;
    const int tx = tid & 15, ty = tid >> 4;
    const int lm = tid >> 1, lk = (tid & 1) * 4;

    const float* Arow;
    if (LAYER == 0) {
        int m = tm + lm;
        int b = m & 63, t = m >> 6;               // x layout [b][t][i]
        Arow = X + (size_t)(b * TT + t) * K;
    } else {
        Arow = g_hseq0 + (size_t)(tm + lm) * K;   // [t][b][k]
    }
    const float* Brow = Wr + (size_t)(tn + lm) * K;

    unsigned long long acc2[8][4];
#pragma unroll
    for (int r = 0; r < 8; r++)
#pragma unroll
        for (int c = 0; c < 4; c++) acc2[r][c] = 0ull;

    const float4 bias0 = *(const float4*)&bias[tn + tx * 8];
    const float4 bias1 = *(const float4*)&bias[tn + tx * 8 + 4];

    for (int k0 = 0; k0 < K; k0 += 8) {
        float4 av = *(const float4*)(Arow + k0 + lk);
        float4 bv = *(const float4*)(Brow + k0 + lk);
        __syncthreads();
        As2[lk + 0][lm] = make_float2(av.x, av.x);
        As2[lk + 1][lm] = make_float2(av.y, av.y);
        As2[lk + 2][lm] = make_float2(av.z, av.z);
        As2[lk + 3][lm] = make_float2(av.w, av.w);
        Bs[lk + 0][lm] = bv.x; Bs[lk + 1][lm] = bv.y;
        Bs[lk + 2][lm] = bv.z; Bs[lk + 3][lm] = bv.w;
        __syncthreads();
#pragma unroll
        for (int kk = 0; kk < 8; kk++) {
            ulonglong2 a01 = *(const ulonglong2*)&As2[kk][ty * 8 + 0];
            ulonglong2 a23 = *(const ulonglong2*)&As2[kk][ty * 8 + 2];
            ulonglong2 a45 = *(const ulonglong2*)&As2[kk][ty * 8 + 4];
            ulonglong2 a67 = *(const ulonglong2*)&As2[kk][ty * 8 + 6];
            ulonglong2 b03 = *(const ulonglong2*)&Bs[kk][tx * 8];
            ulonglong2 b47 = *(const ulonglong2*)&Bs[kk][tx * 8 + 4];
            unsigned long long ar[8] = {a01.x, a01.y, a23.x, a23.y, a45.x, a45.y, a67.x, a67.y};
            unsigned long long bp[4] = {b03.x, b03.y, b47.x, b47.y};
#pragma unroll
            for (int r = 0; r < 8; r++) {
                ffma2(acc2[r][0], ar[r], bp[0]);
                ffma2(acc2[r][1], ar[r], bp[1]);
                ffma2(acc2[r][2], ar[r], bp[2]);
                ffma2(acc2[r][3], ar[r], bp[3]);
            }
        }
    }

#pragma unroll
    for (int r = 0; r < 8; r++) {
        float2 p0 = unpk(acc2[r][0]), p1 = unpk(acc2[r][1]);
        float2 p2 = unpk(acc2[r][2]), p3 = unpk(acc2[r][3]);
        float4 o0 = make_float4(p0.x + bias0.x, p0.y + bias0.y, p1.x + bias0.z, p1.y + bias0.w);
        float4 o1 = make_float4(p2.x + bias1.x, p2.y + bias1.y, p3.x + bias1.z, p3.y + bias1.w);
        size_t m = (size_t)tm + ty * 8 + r;
        float4* crow = (float4*)(g_gx + m * GG + tn + tx * 8);
        crow[0] = o0;
        crow[1] = o1;
    }
}

// ---------------- persistent recurrence (f32x2, chunked double-buffered staging) -----------
// 128 CTAs x 256 threads. CTA owns 16 gate-cols (4 hidden units j).
// smem: Ws2 (duplicated Whh pairs) 64KB, hs 2x(64k x 64b) 32KB, Cs[2][64][20] 10KB.
template <int LAYER>
__global__ void __launch_bounds__(256, 1) lstm_persist(float* __restrict__ lstm_out) {
    extern __shared__ float smem[];
    float2* Ws2 = (float2*)smem;                  // [512][16] pairs
    float*  hs  = smem + 512 * 16 * 2;            // 2 * 4096 floats
    float*  Cs  = hs + 2 * 4096;                  // [2][64][20]

    const int tid = threadIdx.x;
    const int cta = blockIdx.x;
    const int nbase = cta * 16;
    const int jbase = cta * 4;
    const float* __restrict__ Whh = LAYER ? g_Whh1r : g_Whh0r;

    // GEMM role: split-K x2 (even/odd k), thread tile 4m x 2n
    const int kh = tid >> 7;            // 0/1
    const int t2 = tid & 127;
    const int n2 = t2 & 7;              // column pair index (cols 2n2, 2n2+1)
    const int m0 = (t2 >> 3) * 4;       // 4 batch rows
    // pointwise role
    const int pm = tid >> 2;            // batch 0..63
    const int jl = tid & 3;             // unit 0..3

    // stage duplicated Whh slice once: Ws2[k][nl] = (w,w)
    for (int i = tid; i < 512 * 16; i += 256) {
        int k = i & 511, nl = i >> 9;
        float w = Whh[(size_t)(nbase + nl) * HH + k];
        Ws2[k * 16 + nl] = make_float2(w, w);
    }

    float c_reg = 0.f;

    for (int t = 0; t < TT; ++t) {
        if (t > 0) {
            const float4* hsrc = (const float4*)(g_hT + ((t - 1) & 1) * (HH * BB));
            // prologue: stage chunk 0
            float4 p0 = __ldcg(hsrc + tid);
            float4 p1 = __ldcg(hsrc + tid + 256);
            float4 p2 = __ldcg(hsrc + tid + 512);
            float4 p3 = __ldcg(hsrc + tid + 768);
            {
                float4* d = (float4*)hs;
                d[tid] = p0; d[tid + 256] = p1; d[tid + 512] = p2; d[tid + 768] = p3;
            }
            __syncthreads();

            unsigned long long aA = 0, aB = 0, aC = 0, aD = 0;
#pragma unroll
            for (int c = 0; c < 8; c++) {
                if (c < 7) {
                    const float4* s = hsrc + (c + 1) * 1024;
                    p0 = __ldcg(s + tid);
                    p1 = __ldcg(s + tid + 256);
                    p2 = __ldcg(s + tid + 512);
                    p3 = __ldcg(s + tid + 768);
                }
                const float2* wp = Ws2 + (c * 64 + kh) * 16 + n2 * 2;
                const float*  hp = hs + (c & 1) * 4096 + kh * 64 + m0;
#pragma unroll
                for (int i = 0; i < 32; i++) {
                    ulonglong2 w2 = *(const ulonglong2*)(wp + i * 32);
                    ulonglong2 h2 = *(const ulonglong2*)(hp + i * 128);
                    ffma2(aA, h2.x, w2.x);
                    ffma2(aB, h2.y, w2.x);
                    ffma2(aC, h2.x, w2.y);
                    ffma2(aD, h2.y, w2.y);
                }
                if (c < 7) {
                    float4* d = (float4*)(hs + ((c + 1) & 1) * 4096);
                    d[tid] = p0; d[tid + 256] = p1; d[tid + 512] = p2; d[tid + 768] = p3;
                    __syncthreads();
                }
            }

            float2 vA = unpk(aA), vB = unpk(aB), vC = unpk(aC), vD = unpk(aD);
            float* cr = Cs + (kh * 64 + m0) * 20 + n2 * 2;
            cr[0]  = vA.x; cr[1]       = vC.x;
            cr[20] = vA.y; cr[21]      = vC.y;
            cr[40] = vB.x; cr[41]      = vC.x * 0.f + vD.x;  // (kept simple below)
            cr[60] = vB.y; cr[61]      = vD.y;
            // fix row for m0+2 col n+1 (written above as vD.x)
            __syncthreads();
        }

        // gate pre-activations
        float4 gg = *(const float4*)(g_gx + (((size_t)t * BB + pm) * GG + nbase + 4 * jl));
        if (t > 0) {
            float4 c0 = *(const float4*)&Cs[pm * 20 + 4 * jl];
            float4 c1 = *(const float4*)&Cs[(64 + pm) * 20 + 4 * jl];
            gg.x += c0.x + c1.x;
            gg.y += c0.y + c1.y;
            gg.z += c0.z + c1.z;
            gg.w += c0.w + c1.w;
        }

        float si = 1.f / (1.f + expf(-gg.x));
        float sf = 1.f / (1.f + expf(-gg.y));
        float tg = tanhf(gg.z);
        float so = 1.f / (1.f + expf(-gg.w));
        c_reg = fmaf(sf, c_reg, si * tg);
        float hn = so * tanhf(c_reg);

        int j = jbase + jl;
        g_hT[(t & 1) * (HH * BB) + j * 64 + pm] = hn;
        if (LAYER == 0) g_hseq0[((size_t)t * BB + pm) * HH + j] = hn;      // [t][b][j]
        else            lstm_out[((size_t)pm * TT + t) * HH + j] = hn;     // [b][t][j]
        if (t == TT - 1) {
            g_h[LAYER * (BB * HH) + pm * HH + j] = hn;
            g_c[LAYER * (BB * HH) + pm * HH + j] = c_reg;
        }

        // grid barrier
        __syncthreads();
        if (tid == 0) {
            __threadfence();
            unsigned target = (unsigned)NCTA * (unsigned)(t + 1);
            unsigned a = atomicAdd(&g_ctr[LAYER], 1u) + 1u;
            if (a < target) {
                volatile unsigned* p = &g_ctr[LAYER];
                while (*p < target) __nanosleep(64);
            }
            __threadfence();
        }
        __syncthreads();
    }
}

// ---------------- epilogue ----------------
__global__ void out_proj(const float* __restrict__ Wout, const float* __restrict__ bout,
                         float* __restrict__ out) {
    int b = blockIdx.x;
    int o = threadIdx.x;
    const float4* hrow = (const float4*)(g_h + BB * HH + b * HH);
    const float4* w = (const float4*)(Wout + o * HH);
    float s = 0.f;
#pragma unroll 4
    for (int k = 0; k < HH / 4; k++) {
        float4 hv = hrow[k];
        float4 wv = w[k];
        s = fmaf(hv.x, wv.x, s);
        s = fmaf(hv.y, wv.y, s);
        s = fmaf(hv.z, wv.z, s);
        s = fmaf(hv.w, wv.w, s);
    }
    out[b * OO + o] = s + bout[o];
}

__global__ void copy_states(float* __restrict__ hidden, float* __restrict__ cell) {
    int idx = blockIdx.x * blockDim.x + threadIdx.x;
    if (idx < 2 * BB * HH) {
        hidden[idx] = g_h[idx];
        cell[idx]   = g_c[idx];
    }
}

// ---------------- launch ----------------
extern "C" void kernel_launch(void* const* d_in, const int* in_sizes, int n_in,
                              void* d_out, int out_size) {
    const float* x     = (const float*)d_in[0];
    const float* W_ih0 = (const float*)d_in[1];
    const float* W_hh0 = (const float*)d_in[2];
    const float* b_ih0 = (const float*)d_in[3];
    const float* b_hh0 = (const float*)d_in[4];
    const float* W_ih1 = (const float*)d_in[5];
    const float* W_hh1 = (const float*)d_in[6];
    const float* b_ih1 = (const float*)d_in[7];
    const float* b_hh1 = (const float*)d_in[8];
    const float* W_out = (const float*)d_in[9];
    const float* b_out = (const float*)d_in[10];

    float* out      = (float*)d_out;
    float* lstm_out = out + BB * OO;
    float* hidden   = lstm_out + (size_t)BB * TT * HH;
    float* cell     = hidden + 2 * BB * HH;

    const int SMEM = (512 * 16 * 2 + 2 * 4096 + 2 * 64 * 20) * 4;   // 108,544 B
    cudaFuncSetAttribute(lstm_persist<0>, cudaFuncAttributeMaxDynamicSharedMemorySize, SMEM);
    cudaFuncSetAttribute(lstm_persist<1>, cudaFuncAttributeMaxDynamicSharedMemorySize, SMEM);

    prep_misc<<<(2 * GG + 255) / 256, 256>>>(b_ih0, b_hh0, b_ih1, b_hh1);
    reorder_all<<<(GG * DI + 3 * GG * HH + 255) / 256, 256>>>(W_ih0, W_hh0, W_ih1, W_hh1);

    gemm_input<0><<<dim3(GG / 128, (TT * BB) / 128), 256>>>(x);
    lstm_persist<0><<<NCTA, 256, SMEM>>>(lstm_out);

    gemm_input<1><<<dim3(GG / 128, (TT * BB) / 128), 256>>>(x);
    lstm_persist<1><<<NCTA, 256, SMEM>>>(lstm_out);

    out_proj<<<BB, OO>>>(W_out, b_out, out);
    copy_states<<<(2 * BB * HH + 255) / 256, 256>>>(hidden, cell);
}

// round 8
// speedup vs baseline: 1.0544x; 1.0027x over previous
#include <cuda_runtime.h>
#include <math.h>

#define BB 64
#define TT 512
#define DI 256
#define HH 512
#define GG 2048   // 4*HH
#define OO 128
#define NCTA 128  // persistent grid

// ---------------- scratch (static device globals) ----------------
__device__ float g_gx[(size_t)TT * BB * GG];     // [t][b][n], n = j*4+gate
__device__ float g_hseq0[(size_t)TT * BB * HH];  // layer0 h sequence [t][b][j]
__device__ float g_Wih0r[GG * DI];
__device__ float g_Whh0r[GG * HH];
__device__ float g_Wih1r[GG * HH];
__device__ float g_Whh1r[GG * HH];
__device__ float g_bias0[GG];
__device__ float g_bias1[GG];
__device__ float g_h[2 * BB * HH];
__device__ float g_c[2 * BB * HH];
__device__ float g_hT[2 * HH * BB];              // ping-pong h transposed [buf][j][b]
__device__ unsigned g_ctr[2];

// ---------------- f32x2 helpers ----------------
__device__ __forceinline__ void ffma2(unsigned long long& acc, unsigned long long a,
                                      unsigned long long b) {
    asm("fma.rn.f32x2 %0, %1, %2, %0;" : "+l"(acc) : "l"(a), "l"(b));
}
__device__ __forceinline__ float2 unpk(unsigned long long v) {
    float2 r;
    asm("mov.b64 {%0, %1}, %2;" : "=f"(r.x), "=f"(r.y) : "l"(v));
    return r;
}

// ---------------- prep: barrier ctrs + folded biases ----------------
__global__ void prep_misc(const float* __restrict__ bi0, const float* __restrict__ bh0,
                          const float* __restrict__ bi1, const float* __restrict__ bh1) {
    int idx = blockIdx.x * blockDim.x + threadIdx.x;
    if (idx < 2) g_ctr[idx] = 0u;
    if (idx < GG) {
        int g = idx >> 9, j = idx & 511;
        g_bias0[j * 4 + g] = bi0[idx] + bh0[idx];
    } else if (idx < 2 * GG) {
        int n = idx - GG;
        int g = n >> 9, j = n & 511;
        g_bias1[j * 4 + g] = bi1[n] + bh1[n];
    }
}

// ---------------- all weight reorders in one kernel ----------------
__global__ void reorder_all(const float* __restrict__ Wih0, const float* __restrict__ Whh0,
                            const float* __restrict__ Wih1, const float* __restrict__ Whh1) {
    int idx = blockIdx.x * blockDim.x + threadIdx.x;
    if (idx < GG * DI) {
        int k = idx % DI, n_old = idx / DI;
        int g = n_old >> 9, j = n_old & 511;
        g_Wih0r[(j * 4 + g) * DI + k] = Wih0[idx];
        return;
    }
    idx -= GG * DI;
    if (idx < GG * HH) {
        int k = idx % HH, n_old = idx / HH;
        int g = n_old >> 9, j = n_old & 511;
        g_Whh0r[(j * 4 + g) * HH + k] = Whh0[idx];
        return;
    }
    idx -= GG * HH;
    if (idx < GG * HH) {
        int k = idx % HH, n_old = idx / HH;
        int g = n_old >> 9, j = n_old & 511;
        g_Wih1r[(j * 4 + g) * HH + k] = Wih1[idx];
        return;
    }
    idx -= GG * HH;
    if (idx < GG * HH) {
        int k = idx % HH, n_old = idx / HH;
        int g = n_old >> 9, j = n_old & 511;
        g_Whh1r[(j * 4 + g) * HH + k] = Whh1[idx];
    }
}

// ---------------- input GEMM (f32x2): gx[m][n] = A[m,:].Wr[n,:] + bias[n] ----------------
template <int LAYER>
__global__ void __launch_bounds__(256) gemm_input(const float* __restrict__ X) {
    constexpr int K = (LAYER == 0) ? DI : HH;
    const float* __restrict__ Wr   = (LAYER == 0) ? g_Wih0r : g_Wih1r;
    const float* __restrict__ bias = (LAYER == 0) ? g_bias0 : g_bias1;

    __shared__ float2 As2[8][128];   // duplicated pairs (a,a)
    __shared__ float  Bs[8][128];

    const int tm = blockIdx.y * 128, tn = blockIdx.x * 128;
    const int tid = threadIdx.x;
    const int tx = tid & 15, ty = tid >> 4;
    const int lm = tid >> 1, lk = (tid & 1) * 4;

    const float* Arow;
    if (LAYER == 0) {
        int m = tm + lm;
        int b = m & 63, t = m >> 6;               // x layout [b][t][i]
        Arow = X + (size_t)(b * TT + t) * K;
    } else {
        Arow = g_hseq0 + (size_t)(tm + lm) * K;   // [t][b][k]
    }
    const float* Brow = Wr + (size_t)(tn + lm) * K;

    unsigned long long acc2[8][4];
#pragma unroll
    for (int r = 0; r < 8; r++)
#pragma unroll
        for (int c = 0; c < 4; c++) acc2[r][c] = 0ull;

    const float4 bias0 = *(const float4*)&bias[tn + tx * 8];
    const float4 bias1 = *(const float4*)&bias[tn + tx * 8 + 4];

    for (int k0 = 0; k0 < K; k0 += 8) {
        float4 av = *(const float4*)(Arow + k0 + lk);
        float4 bv = *(const float4*)(Brow + k0 + lk);
        __syncthreads();
        As2[lk + 0][lm] = make_float2(av.x, av.x);
        As2[lk + 1][lm] = make_float2(av.y, av.y);
        As2[lk + 2][lm] = make_float2(av.z, av.z);
        As2[lk + 3][lm] = make_float2(av.w, av.w);
        Bs[lk + 0][lm] = bv.x; Bs[lk + 1][lm] = bv.y;
        Bs[lk + 2][lm] = bv.z; Bs[lk + 3][lm] = bv.w;
        __syncthreads();
#pragma unroll
        for (int kk = 0; kk < 8; kk++) {
            ulonglong2 a01 = *(const ulonglong2*)&As2[kk][ty * 8 + 0];
            ulonglong2 a23 = *(const ulonglong2*)&As2[kk][ty * 8 + 2];
            ulonglong2 a45 = *(const ulonglong2*)&As2[kk][ty * 8 + 4];
            ulonglong2 a67 = *(const ulonglong2*)&As2[kk][ty * 8 + 6];
            ulonglong2 b03 = *(const ulonglong2*)&Bs[kk][tx * 8];
            ulonglong2 b47 = *(const ulonglong2*)&Bs[kk][tx * 8 + 4];
            unsigned long long ar[8] = {a01.x, a01.y, a23.x, a23.y, a45.x, a45.y, a67.x, a67.y};
            unsigned long long bp[4] = {b03.x, b03.y, b47.x, b47.y};
#pragma unroll
            for (int r = 0; r < 8; r++) {
                ffma2(acc2[r][0], ar[r], bp[0]);
                ffma2(acc2[r][1], ar[r], bp[1]);
                ffma2(acc2[r][2], ar[r], bp[2]);
                ffma2(acc2[r][3], ar[r], bp[3]);
            }
        }
    }

#pragma unroll
    for (int r = 0; r < 8; r++) {
        float2 p0 = unpk(acc2[r][0]), p1 = unpk(acc2[r][1]);
        float2 p2 = unpk(acc2[r][2]), p3 = unpk(acc2[r][3]);
        float4 o0 = make_float4(p0.x + bias0.x, p0.y + bias0.y, p1.x + bias0.z, p1.y + bias0.w);
        float4 o1 = make_float4(p2.x + bias1.x, p2.y + bias1.y, p3.x + bias1.z, p3.y + bias1.w);
        size_t m = (size_t)tm + ty * 8 + r;
        float4* crow = (float4*)(g_gx + m * GG + tn + tx * 8);
        crow[0] = o0;
        crow[1] = o1;
    }
}

// ---------------- persistent recurrence (f32x2, chunked double-buffered staging) -----------
// 128 CTAs x 256 threads. CTA owns 16 gate-cols (4 hidden units j).
// smem: Ws2 (duplicated Whh pairs) 64KB, hs 2x(64k x 64b) 32KB, Cs[2][64][20] 10KB.
template <int LAYER>
__global__ void __launch_bounds__(256, 1) lstm_persist(float* __restrict__ lstm_out) {
    extern __shared__ float smem[];
    float2* Ws2 = (float2*)smem;                  // [512][16] pairs
    float*  hs  = smem + 512 * 16 * 2;            // 2 * 4096 floats
    float*  Cs  = hs + 2 * 4096;                  // [2][64][20]

    const int tid = threadIdx.x;
    const int cta = blockIdx.x;
    const int nbase = cta * 16;
    const int jbase = cta * 4;
    const float* __restrict__ Whh = LAYER ? g_Whh1r : g_Whh0r;

    // GEMM role: split-K x2 (even/odd k), thread tile 4m x 2n
    const int kh = tid >> 7;            // 0/1
    const int t2 = tid & 127;
    const int n2 = t2 & 7;              // column pair index (cols 2n2, 2n2+1)
    const int m0 = (t2 >> 3) * 4;       // 4 batch rows
    // pointwise role
    const int pm = tid >> 2;            // batch 0..63
    const int jl = tid & 3;             // unit 0..3

    // stage duplicated Whh slice once: Ws2[k][nl] = (w,w)
    for (int i = tid; i < 512 * 16; i += 256) {
        int k = i & 511, nl = i >> 9;
        float w = Whh[(size_t)(nbase + nl) * HH + k];
        Ws2[k * 16 + nl] = make_float2(w, w);
    }

    float c_reg = 0.f;

    for (int t = 0; t < TT; ++t) {
        if (t > 0) {
            const float4* hsrc = (const float4*)(g_hT + ((t - 1) & 1) * (HH * BB));
            // prologue: stage chunk 0
            float4 p0 = __ldcg(hsrc + tid);
            float4 p1 = __ldcg(hsrc + tid + 256);
            float4 p2 = __ldcg(hsrc + tid + 512);
            float4 p3 = __ldcg(hsrc + tid + 768);
            {
                float4* d = (float4*)hs;
                d[tid] = p0; d[tid + 256] = p1; d[tid + 512] = p2; d[tid + 768] = p3;
            }
            __syncthreads();

            unsigned long long aA = 0, aB = 0, aC = 0, aD = 0;
#pragma unroll
            for (int c = 0; c < 8; c++) {
                if (c < 7) {
                    const float4* s = hsrc + (c + 1) * 1024;
                    p0 = __ldcg(s + tid);
                    p1 = __ldcg(s + tid + 256);
                    p2 = __ldcg(s + tid + 512);
                    p3 = __ldcg(s + tid + 768);
                }
                const float2* wp = Ws2 + (c * 64 + kh) * 16 + n2 * 2;
                const float*  hp = hs + (c & 1) * 4096 + kh * 64 + m0;
#pragma unroll
                for (int i = 0; i < 32; i++) {
                    ulonglong2 w2 = *(const ulonglong2*)(wp + i * 32);
                    ulonglong2 h2 = *(const ulonglong2*)(hp + i * 128);
                    ffma2(aA, h2.x, w2.x);
                    ffma2(aB, h2.y, w2.x);
                    ffma2(aC, h2.x, w2.y);
                    ffma2(aD, h2.y, w2.y);
                }
                if (c < 7) {
                    float4* d = (float4*)(hs + ((c + 1) & 1) * 4096);
                    d[tid] = p0; d[tid + 256] = p1; d[tid + 512] = p2; d[tid + 768] = p3;
                    __syncthreads();
                }
            }

            float2 vA = unpk(aA), vB = unpk(aB), vC = unpk(aC), vD = unpk(aD);
            float* cr = Cs + (kh * 64 + m0) * 20 + n2 * 2;
            cr[0]  = vA.x; cr[1]       = vC.x;
            cr[20] = vA.y; cr[21]      = vC.y;
            cr[40] = vB.x; cr[41]      = vC.x * 0.f + vD.x;  // (kept simple below)
            cr[60] = vB.y; cr[61]      = vD.y;
            // fix row for m0+2 col n+1 (written above as vD.x)
            __syncthreads();
        }

        // gate pre-activations
        float4 gg = *(const float4*)(g_gx + (((size_t)t * BB + pm) * GG + nbase + 4 * jl));
        if (t > 0) {
            float4 c0 = *(const float4*)&Cs[pm * 20 + 4 * jl];
            float4 c1 = *(const float4*)&Cs[(64 + pm) * 20 + 4 * jl];
            gg.x += c0.x + c1.x;
            gg.y += c0.y + c1.y;
            gg.z += c0.z + c1.z;
            gg.w += c0.w + c1.w;
        }

        float si = 1.f / (1.f + expf(-gg.x));
        float sf = 1.f / (1.f + expf(-gg.y));
        float tg = tanhf(gg.z);
        float so = 1.f / (1.f + expf(-gg.w));
        c_reg = fmaf(sf, c_reg, si * tg);
        float hn = so * tanhf(c_reg);

        int j = jbase + jl;
        g_hT[(t & 1) * (HH * BB) + j * 64 + pm] = hn;
        if (LAYER == 0) g_hseq0[((size_t)t * BB + pm) * HH + j] = hn;      // [t][b][j]
        else            lstm_out[((size_t)pm * TT + t) * HH + j] = hn;     // [b][t][j]
        if (t == TT - 1) {
            g_h[LAYER * (BB * HH) + pm * HH + j] = hn;
            g_c[LAYER * (BB * HH) + pm * HH + j] = c_reg;
        }

        // grid barrier
        __syncthreads();
        if (tid == 0) {
            __threadfence();
            unsigned target = (unsigned)NCTA * (unsigned)(t + 1);
            unsigned a = atomicAdd(&g_ctr[LAYER], 1u) + 1u;
            if (a < target) {
                volatile unsigned* p = &g_ctr[LAYER];
                while (*p < target) __nanosleep(64);
            }
            __threadfence();
        }
        __syncthreads();
    }
}

// ---------------- epilogue ----------------
__global__ void out_proj(const float* __restrict__ Wout, const float* __restrict__ bout,
                         float* __restrict__ out) {
    int b = blockIdx.x;
    int o = threadIdx.x;
    const float4* hrow = (const float4*)(g_h + BB * HH + b * HH);
    const float4* w = (const float4*)(Wout + o * HH);
    float s = 0.f;
#pragma unroll 4
    for (int k = 0; k < HH / 4; k++) {
        float4 hv = hrow[k];
        float4 wv = w[k];
        s = fmaf(hv.x, wv.x, s);
        s = fmaf(hv.y, wv.y, s);
        s = fmaf(hv.z, wv.z, s);
        s = fmaf(hv.w, wv.w, s);
    }
    out[b * OO + o] = s + bout[o];
}

__global__ void copy_states(float* __restrict__ hidden, float* __restrict__ cell) {
    int idx = blockIdx.x * blockDim.x + threadIdx.x;
    if (idx < 2 * BB * HH) {
        hidden[idx] = g_h[idx];
        cell[idx]   = g_c[idx];
    }
}

// ---------------- launch ----------------
extern "C" void kernel_launch(void* const* d_in, const int* in_sizes, int n_in,
                              void* d_out, int out_size) {
    const float* x     = (const float*)d_in[0];
    const float* W_ih0 = (const float*)d_in[1];
    const float* W_hh0 = (const float*)d_in[2];
    const float* b_ih0 = (const float*)d_in[3];
    const float* b_hh0 = (const float*)d_in[4];
    const float* W_ih1 = (const float*)d_in[5];
    const float* W_hh1 = (const float*)d_in[6];
    const float* b_ih1 = (const float*)d_in[7];
    const float* b_hh1 = (const float*)d_in[8];
    const float* W_out = (const float*)d_in[9];
    const float* b_out = (const float*)d_in[10];

    float* out      = (float*)d_out;
    float* lstm_out = out + BB * OO;
    float* hidden   = lstm_out + (size_t)BB * TT * HH;
    float* cell     = hidden + 2 * BB * HH;

    const int SMEM = (512 * 16 * 2 + 2 * 4096 + 2 * 64 * 20) * 4;   // 108,544 B
    cudaFuncSetAttribute(lstm_persist<0>, cudaFuncAttributeMaxDynamicSharedMemorySize, SMEM);
    cudaFuncSetAttribute(lstm_persist<1>, cudaFuncAttributeMaxDynamicSharedMemorySize, SMEM);

    prep_misc<<<(2 * GG + 255) / 256, 256>>>(b_ih0, b_hh0, b_ih1, b_hh1);
    reorder_all<<<(GG * DI + 3 * GG * HH + 255) / 256, 256>>>(W_ih0, W_hh0, W_ih1, W_hh1);

    gemm_input<0><<<dim3(GG / 128, (TT * BB) / 128), 256>>>(x);
    lstm_persist<0><<<NCTA, 256, SMEM>>>(lstm_out);

    gemm_input<1><<<dim3(GG / 128, (TT * BB) / 128), 256>>>(x);
    lstm_persist<1><<<NCTA, 256, SMEM>>>(lstm_out);

    out_proj<<<BB, OO>>>(W_out, b_out, out);
    copy_states<<<(2 * BB * HH + 255) / 256, 256>>>(hidden, cell);
}